// round 1
// baseline (speedup 1.0000x reference)
#include <cuda_runtime.h>
#include <math.h>

// ---------------- problem constants ----------------
#define Bsz 4
#define Nn  1025
#define Cc  768
#define Hh  12
#define Dh  64
#define BH  (Bsz*Hh)         // 48
#define NN  ((long)Nn*Nn)    // 1050625
#define KSEL 256             // int(1024*0.25)

// ---------------- scratch (device globals; allocs are forbidden) ----------------
__device__ float g_qkv[(size_t)Bsz*Nn*3*Cc];      // [b,n,3,H,Dh]  ~37.8 MB
__device__ float g_S  [(size_t)BH*Nn*Nn];         // attn scores/probs ~202 MB
__device__ float g_ctx[(size_t)Bsz*Nn*Cc];        // context in [b,n,h*Dh] layout
__device__ float g_patch[BH*Nn];                  // column sums per (b,h)
__device__ float g_gucb[Bsz*(Nn-1)];              // global ucb per batch
__device__ float g_keep[Bsz*Nn];                  // keep mask
__device__ float g_cnt[Nn];                       // selection counts

// ---------------- generic strided-batch SGEMM ----------------
// C[m,n] = alpha * sum_k A[m,k]*B[k,n] (+bias[n])
// A elem (m,k) at A + m*lda + k*sda ; B elem (k,n) at B + k*ldb + n*sdb
// batch z: b1=z/divH, b2=z%divH; pointers offset by b1*off1 + b2*off2.
__global__ __launch_bounds__(256)
void sgemm_kernel(const float* __restrict__ A, const float* __restrict__ B,
                  const float* __restrict__ bias, float* __restrict__ C,
                  int M, int N, int K,
                  long lda, long sda, long offA1, long offA2,
                  long ldb, long sdb, long offB1, long offB2,
                  long ldc, long offC1, long offC2,
                  int divH, float alpha)
{
    int z  = blockIdx.z;
    int zb = z / divH, zh = z % divH;
    A += (size_t)zb * offA1 + (size_t)zh * offA2;
    B += (size_t)zb * offB1 + (size_t)zh * offB2;
    C += (size_t)zb * offC1 + (size_t)zh * offC2;

    __shared__ float As[16][68];
    __shared__ float Bs[16][68];

    const int tid = threadIdx.x;
    const int tx = tid & 15, ty = tid >> 4;
    const int m0 = blockIdx.y * 64, n0 = blockIdx.x * 64;

    float acc[4][4] = {};

    for (int k0 = 0; k0 < K; k0 += 16) {
        // ---- load A tile (64m x 16k) ----
        if (sda == 1) {
            #pragma unroll
            for (int t = tid; t < 64*16; t += 256) {
                int m = t >> 4, k = t & 15;
                int gm = m0 + m, gk = k0 + k;
                As[k][m] = (gm < M && gk < K) ? A[(size_t)gm*lda + gk] : 0.f;
            }
        } else {
            #pragma unroll
            for (int t = tid; t < 64*16; t += 256) {
                int k = t >> 6, m = t & 63;
                int gm = m0 + m, gk = k0 + k;
                As[k][m] = (gm < M && gk < K) ? A[(size_t)gm*lda + (size_t)gk*sda] : 0.f;
            }
        }
        // ---- load B tile (16k x 64n) ----
        if (sdb == 1) {
            #pragma unroll
            for (int t = tid; t < 64*16; t += 256) {
                int k = t >> 6, n = t & 63;
                int gk = k0 + k, gn = n0 + n;
                Bs[k][n] = (gk < K && gn < N) ? B[(size_t)gk*ldb + gn] : 0.f;
            }
        } else {
            #pragma unroll
            for (int t = tid; t < 64*16; t += 256) {
                int n = t >> 4, k = t & 15;
                int gk = k0 + k, gn = n0 + n;
                Bs[k][n] = (gk < K && gn < N) ? B[(size_t)gk*ldb + (size_t)gn*sdb] : 0.f;
            }
        }
        __syncthreads();

        #pragma unroll
        for (int kk = 0; kk < 16; kk++) {
            float a[4], b[4];
            #pragma unroll
            for (int i = 0; i < 4; i++) a[i] = As[kk][ty*4 + i];
            #pragma unroll
            for (int j = 0; j < 4; j++) b[j] = Bs[kk][tx*4 + j];
            #pragma unroll
            for (int i = 0; i < 4; i++)
                #pragma unroll
                for (int j = 0; j < 4; j++)
                    acc[i][j] = fmaf(a[i], b[j], acc[i][j]);
        }
        __syncthreads();
    }

    #pragma unroll
    for (int i = 0; i < 4; i++) {
        int gm = m0 + ty*4 + i;
        if (gm >= M) continue;
        #pragma unroll
        for (int j = 0; j < 4; j++) {
            int gn = n0 + tx*4 + j;
            if (gn >= N) continue;
            float v = acc[i][j] * alpha;
            if (bias) v += bias[gn];
            C[(size_t)gm*ldc + gn] = v;
        }
    }
}

// ---------------- row softmax over N=1025 ----------------
__global__ __launch_bounds__(256)
void softmax_kernel(float* __restrict__ S)
{
    float* row = S + (size_t)blockIdx.x * Nn;
    __shared__ float red[256];
    int t = threadIdx.x;

    float mx = -INFINITY;
    for (int j = t; j < Nn; j += 256) mx = fmaxf(mx, row[j]);
    red[t] = mx; __syncthreads();
    for (int s = 128; s > 0; s >>= 1) { if (t < s) red[t] = fmaxf(red[t], red[t+s]); __syncthreads(); }
    mx = red[0]; __syncthreads();

    float sm = 0.f;
    for (int j = t; j < Nn; j += 256) { float e = expf(row[j] - mx); row[j] = e; sm += e; }
    red[t] = sm; __syncthreads();
    for (int s = 128; s > 0; s >>= 1) { if (t < s) red[t] += red[t+s]; __syncthreads(); }
    float inv = 1.f / red[0];
    for (int j = t; j < Nn; j += 256) row[j] *= inv;
}

// ---------------- zero small scratch ----------------
__global__ void zero_scratch_kernel()
{
    int idx = blockIdx.x * 256 + threadIdx.x;
    if (idx < BH*Nn) g_patch[idx] = 0.f;
    if (idx < Bsz*Nn) g_keep[idx] = 0.f;
    if (idx < Nn) g_cnt[idx] = 0.f;
}

// ---------------- column sums of attn per (b,h) (grid.y = i-chunks) ----------------
__global__ __launch_bounds__(256)
void colsum_kernel(const float* __restrict__ S)
{
    int bh = blockIdx.x;
    int i0 = blockIdx.y * 129;
    int i1 = min(i0 + 129, Nn);
    const float* Sb = S + (size_t)bh * NN;
    int t = threadIdx.x;

    float acc[5] = {0.f, 0.f, 0.f, 0.f, 0.f};
    for (int i = i0; i < i1; i++) {
        const float* row = Sb + (size_t)i * Nn;
        #pragma unroll
        for (int r = 0; r < 5; r++) { int j = t + 256*r; if (j < Nn) acc[r] += row[j]; }
    }
    #pragma unroll
    for (int r = 0; r < 5; r++) { int j = t + 256*r; if (j < Nn) atomicAdd(&g_patch[bh*Nn + j], acc[r]); }
}

// ---------------- combine patch means + exploration -> global_ucb ----------------
__global__ __launch_bounds__(256)
void ucb_combine_kernel(const float* __restrict__ ucb_score, const int* __restrict__ counter)
{
    int b = blockIdx.x, t = threadIdx.x;
    float logc = logf((float)(*counter) + 1.0f);
    for (int jj = t; jj < Nn-1; jj += 256) {
        int j = jj + 1;
        float s = 0.f;
        #pragma unroll
        for (int h = 0; h < Hh; h++) {
            float expl = sqrtf(logc / (ucb_score[h*Nn + j] + 1e-6f));   // BETA=1
            s += g_patch[(b*Hh + h)*Nn + j] * (1.f/(float)Nn) + expl;
        }
        g_gucb[b*(Nn-1) + jj] = s * (1.f/(float)Hh);
    }
}

// ---------------- exact top-k via bitonic sort (ties -> lower index, like jax) ----------------
__global__ __launch_bounds__(512)
void topk_kernel()
{
    __shared__ float sv[1024];
    __shared__ int   si[1024];
    int b = blockIdx.x, t = threadIdx.x;

    for (int j = t; j < 1024; j += 512) { sv[j] = g_gucb[b*1024 + j]; si[j] = j; }
    __syncthreads();

    for (int k = 2; k <= 1024; k <<= 1) {
        for (int j = k >> 1; j > 0; j >>= 1) {
            for (int i = t; i < 1024; i += 512) {
                int ixj = i ^ j;
                if (ixj > i) {
                    float v1 = sv[i], v2 = sv[ixj];
                    int  i1 = si[i],  i2 = si[ixj];
                    // strict order "v1 before v2" in DESCENDING sort:
                    bool before = (v1 > v2) || (v1 == v2 && i1 < i2);
                    bool dirDesc = ((i & k) == 0);
                    bool doSwap = dirDesc ? (!before) : before;
                    if (doSwap) { sv[i] = v2; sv[ixj] = v1; si[i] = i2; si[ixj] = i1; }
                }
            }
            __syncthreads();
        }
    }

    if (t < KSEL) {
        int tok = si[t] + 1;              // +1 for CLS shift
        g_keep[b*Nn + tok] = 1.f;
        atomicAdd(&g_cnt[tok], 1.f);
    }
    if (t == 0) g_keep[b*Nn + 0] = 1.f;   // CLS always kept
}

// ---------------- apply prune mask + renormalize rows in place ----------------
__global__ __launch_bounds__(256)
void mask_renorm_kernel(float* __restrict__ S, const int* __restrict__ counter,
                        const int* __restrict__ enabled)
{
    if (!((*enabled) != 0 && (*counter) > 50)) return;   // non-UCB path: attn used as-is
    long r = blockIdx.x;                 // (bh * Nn + i)
    int bh = (int)(r / Nn);
    int b  = bh / Hh;
    int i  = (int)(r % Nn);

    float* row = S + (size_t)r * Nn;
    const float* kp = g_keep + b*Nn;
    bool keepi = kp[i] > 0.5f;
    int t = threadIdx.x;
    __shared__ float red[256];

    float sm = 0.f;
    if (keepi) {
        for (int j = t; j < Nn; j += 256) sm += row[j];
    } else {
        for (int j = t; j < Nn; j += 256) { float w = row[j] * kp[j]; row[j] = w; sm += w; }
    }
    red[t] = sm; __syncthreads();
    for (int s = 128; s > 0; s >>= 1) { if (t < s) red[t] += red[t+s]; __syncthreads(); }
    float inv = 1.f / (red[0] + 1e-8f);
    for (int j = t; j < Nn; j += 256) row[j] *= inv;
}

// ---------------- score_delta = broadcast(cnt / B) to [H,N] ----------------
__global__ void score_delta_kernel(float* __restrict__ out2)
{
    int idx = blockIdx.x * 256 + threadIdx.x;
    if (idx < Hh*Nn) out2[idx] = g_cnt[idx % Nn] * (1.f / (float)Bsz);
}

// =======================================================================
extern "C" void kernel_launch(void* const* d_in, const int* in_sizes, int n_in,
                              void* d_out, int out_size)
{
    const float* x      = (const float*)d_in[0];
    const float* ucbsc  = (const float*)d_in[1];
    const float* Wqkv   = (const float*)d_in[2];
    const float* Wproj  = (const float*)d_in[3];
    const float* bproj  = (const float*)d_in[4];
    const int*   counter = (const int*)d_in[5];
    const int*   enabled = (const int*)d_in[6];
    float* out = (float*)d_out;

    float *qkv, *S, *ctx;
    cudaGetSymbolAddress((void**)&qkv, g_qkv);
    cudaGetSymbolAddress((void**)&S,   g_S);
    cudaGetSymbolAddress((void**)&ctx, g_ctx);

    const long qkvRow = 3L*Cc;            // 2304
    const long qkvB   = (long)Nn*3*Cc;    // per-batch stride in qkv
    const float scale = 0.125f;           // Dh^-0.5

    // 1) qkv = x @ W_qkv    [4100 x 2304 x 768]
    {
        dim3 grid((3*Cc+63)/64, (Bsz*Nn+63)/64, 1);
        sgemm_kernel<<<grid, 256>>>(x, Wqkv, nullptr, qkv,
            Bsz*Nn, 3*Cc, Cc,
            Cc, 1, 0, 0,
            3L*Cc, 1, 0, 0,
            3L*Cc, 0, 0, 1, 1.0f);
    }
    // 2) S = scale * Q @ K^T  per (b,h)   [1025 x 1025 x 64] x48
    {
        dim3 grid((Nn+63)/64, (Nn+63)/64, BH);
        sgemm_kernel<<<grid, 256>>>(qkv /*t=0*/, qkv + Cc /*t=1*/, nullptr, S,
            Nn, Nn, Dh,
            qkvRow, 1, qkvB, Dh,          // A: q  (i,d)
            1, qkvRow, qkvB, Dh,          // B: k^T (d,j) -> k[j,d]
            Nn, (long)Hh*NN, NN, Hh, scale);
    }
    // 3) softmax rows
    softmax_kernel<<<BH*Nn, 256>>>(S);

    // 4) zero small scratch, column sums, ucb combine, top-k
    zero_scratch_kernel<<<(BH*Nn + 255)/256, 256>>>();
    { dim3 grid(BH, 8); colsum_kernel<<<grid, 256>>>(S); }
    ucb_combine_kernel<<<Bsz, 256>>>(ucbsc, counter);
    topk_kernel<<<Bsz, 512>>>();

    // 5) mask + renormalize in place
    mask_renorm_kernel<<<BH*Nn, 256>>>(S, counter, enabled);

    // 6) ctx[b,i,h*Dh+d] = pruned @ V   per (b,h)  [1025 x 64 x 1025] x48
    {
        dim3 grid(1, (Nn+63)/64, BH);
        sgemm_kernel<<<grid, 256>>>(S, qkv + 2L*Cc /*t=2*/, nullptr, ctx,
            Nn, Dh, Nn,
            Nn, 1, (long)Hh*NN, NN,       // A: pruned S
            qkvRow, 1, qkvB, Dh,          // B: v (j,d)
            Cc, (long)Nn*Cc, Dh, Hh, 1.0f);
    }
    // 7) out = ctx @ W_proj + b_proj   [4100 x 768 x 768]
    {
        dim3 grid((Cc+63)/64, (Bsz*Nn+63)/64, 1);
        sgemm_kernel<<<grid, 256>>>(ctx, Wproj, bproj, out,
            Bsz*Nn, Cc, Cc,
            Cc, 1, 0, 0,
            Cc, 1, 0, 0,
            Cc, 0, 0, 1, 1.0f);
    }
    // 8) score_delta
    if (out_size >= Bsz*Nn*Cc + Hh*Nn) {
        score_delta_kernel<<<(Hh*Nn + 255)/256, 256>>>(out + (size_t)Bsz*Nn*Cc);
    }
}

// round 2
// speedup vs baseline: 1.3550x; 1.3550x over previous
#include <cuda_runtime.h>
#include <math.h>

// ---------------- problem constants ----------------
#define Bsz 4
#define Nn  1025
#define Cc  768
#define Hh  12
#define Dh  64
#define BH  (Bsz*Hh)           // 48
#define SLD 1028               // padded row stride for S (float4-aligned)
#define SB  ((size_t)Nn*SLD)   // per-(b,h) slab size in S
#define KSEL 256               // int(1024*0.25)

// ---------------- scratch (device globals; allocs forbidden) ----------------
__device__ float g_qkv[(size_t)Bsz*Nn*3*Cc];      // [b,n,3,H,Dh]
__device__ float g_S  [(size_t)BH*Nn*SLD];        // attn probs (padded rows) ~202MB
__device__ float g_ctx[(size_t)Bsz*Nn*Cc];        // context [b,n,h*Dh]
__device__ float g_patch[BH*Nn];                  // column sums per (b,h)
__device__ float g_gucb[Bsz*(Nn-1)];              // global ucb per batch
__device__ float g_keep[Bsz*Nn];                  // keep mask
__device__ float g_cnt[Nn];                       // selection counts

// =====================================================================
// gemm_nn: C[M,N] = A[M,K] @ B[K,N] (+bias). 128x128 tile, 8x8 micro,
// BK=8, double-buffered. Requires N%128==0, K%8==0, lda/ldb/ldc %4==0.
// =====================================================================
template<bool BIAS>
__global__ __launch_bounds__(256)
void gemm_nn(const float* __restrict__ A, const float* __restrict__ B,
             const float* __restrict__ bias, float* __restrict__ C,
             int M, int N, int K, int lda, int ldb, int ldc)
{
    __shared__ float As[2][8][132];
    __shared__ float Bs[2][8][128];
    const int tid = threadIdx.x;
    const int m0 = blockIdx.y * 128, n0 = blockIdx.x * 128;
    const int a_m = tid >> 1, a_k = (tid & 1) << 2;
    const int b_k = tid >> 5, b_n = (tid & 31) << 2;
    const bool a_ok = (m0 + a_m) < M;
    const float* Ap = A + (size_t)(m0 + a_m) * lda + a_k;
    const float* Bp = B + (size_t)b_k * ldb + n0 + b_n;

    float4 af = a_ok ? *(const float4*)Ap : make_float4(0.f,0.f,0.f,0.f);
    float4 bf = *(const float4*)Bp;
    As[0][a_k+0][a_m]=af.x; As[0][a_k+1][a_m]=af.y;
    As[0][a_k+2][a_m]=af.z; As[0][a_k+3][a_m]=af.w;
    *(float4*)&Bs[0][b_k][b_n] = bf;
    __syncthreads();

    const int tx = tid & 15, ty = tid >> 4;
    float acc[8][8];
    #pragma unroll
    for (int i=0;i<8;i++)
        #pragma unroll
        for (int j=0;j<8;j++) acc[i][j]=0.f;

    const int nk = K >> 3;
    for (int t = 0; t < nk; t++) {
        const int cur = t & 1;
        if (t + 1 < nk) {
            af = a_ok ? *(const float4*)(Ap + (t+1)*8) : make_float4(0.f,0.f,0.f,0.f);
            bf = *(const float4*)(Bp + (size_t)(t+1)*8*ldb);
        }
        #pragma unroll
        for (int kk = 0; kk < 8; kk++) {
            float a[8], b[8];
            *(float4*)&a[0] = *(const float4*)&As[cur][kk][ty*8];
            *(float4*)&a[4] = *(const float4*)&As[cur][kk][ty*8+4];
            *(float4*)&b[0] = *(const float4*)&Bs[cur][kk][tx*8];
            *(float4*)&b[4] = *(const float4*)&Bs[cur][kk][tx*8+4];
            #pragma unroll
            for (int i=0;i<8;i++)
                #pragma unroll
                for (int j=0;j<8;j++) acc[i][j] = fmaf(a[i], b[j], acc[i][j]);
        }
        if (t + 1 < nk) {
            const int nxt = cur ^ 1;
            As[nxt][a_k+0][a_m]=af.x; As[nxt][a_k+1][a_m]=af.y;
            As[nxt][a_k+2][a_m]=af.z; As[nxt][a_k+3][a_m]=af.w;
            *(float4*)&Bs[nxt][b_k][b_n] = bf;
            __syncthreads();
        }
    }

    #pragma unroll
    for (int i=0;i<8;i++) {
        int gm = m0 + ty*8 + i;
        if (gm < M) {
            float* cp = C + (size_t)gm*ldc + n0 + tx*8;
            float4 v0, v1;
            v0.x=acc[i][0]; v0.y=acc[i][1]; v0.z=acc[i][2]; v0.w=acc[i][3];
            v1.x=acc[i][4]; v1.y=acc[i][5]; v1.z=acc[i][6]; v1.w=acc[i][7];
            if (BIAS) {
                const float4 bb0 = *(const float4*)&bias[n0+tx*8];
                const float4 bb1 = *(const float4*)&bias[n0+tx*8+4];
                v0.x+=bb0.x; v0.y+=bb0.y; v0.z+=bb0.z; v0.w+=bb0.w;
                v1.x+=bb1.x; v1.y+=bb1.y; v1.z+=bb1.z; v1.w+=bb1.w;
            }
            *(float4*)cp = v0; *(float4*)(cp+4) = v1;
        }
    }
}

// =====================================================================
// gemm_qk: S[bh] = 0.125 * Q @ K^T per (b,h). M=N=1025, K=64.
// Both A and B are [1025 x 64] slabs with row stride 3*Cc.
// =====================================================================
__global__ __launch_bounds__(256)
void gemm_qk(const float* __restrict__ QKV, float* __restrict__ S)
{
    const int bh = blockIdx.z;
    const int b = bh / Hh, h = bh % Hh;
    const float* Q  = QKV + (size_t)b*Nn*3*Cc + (size_t)h*Dh;
    const float* Km = Q + Cc;
    float* Cs = S + (size_t)bh * SB;

    __shared__ float As[2][8][132];
    __shared__ float Bs[2][8][132];
    const int tid = threadIdx.x;
    const int m0 = blockIdx.y * 128, n0 = blockIdx.x * 128;
    const int a_m = tid >> 1, a_k = (tid & 1) << 2;
    const bool a_ok = (m0 + a_m) < Nn;
    const bool b_ok = (n0 + a_m) < Nn;
    const float* Ap = Q  + (size_t)(m0 + a_m)*(3*Cc) + a_k;
    const float* Bp = Km + (size_t)(n0 + a_m)*(3*Cc) + a_k;

    float4 af = a_ok ? *(const float4*)Ap : make_float4(0.f,0.f,0.f,0.f);
    float4 bf = b_ok ? *(const float4*)Bp : make_float4(0.f,0.f,0.f,0.f);
    As[0][a_k+0][a_m]=af.x; As[0][a_k+1][a_m]=af.y;
    As[0][a_k+2][a_m]=af.z; As[0][a_k+3][a_m]=af.w;
    Bs[0][a_k+0][a_m]=bf.x; Bs[0][a_k+1][a_m]=bf.y;
    Bs[0][a_k+2][a_m]=bf.z; Bs[0][a_k+3][a_m]=bf.w;
    __syncthreads();

    const int tx = tid & 15, ty = tid >> 4;
    float acc[8][8];
    #pragma unroll
    for (int i=0;i<8;i++)
        #pragma unroll
        for (int j=0;j<8;j++) acc[i][j]=0.f;

    const int nk = Dh >> 3;   // 8
    for (int t = 0; t < nk; t++) {
        const int cur = t & 1;
        if (t + 1 < nk) {
            af = a_ok ? *(const float4*)(Ap + (t+1)*8) : make_float4(0.f,0.f,0.f,0.f);
            bf = b_ok ? *(const float4*)(Bp + (t+1)*8) : make_float4(0.f,0.f,0.f,0.f);
        }
        #pragma unroll
        for (int kk = 0; kk < 8; kk++) {
            float a[8], b[8];
            *(float4*)&a[0] = *(const float4*)&As[cur][kk][ty*8];
            *(float4*)&a[4] = *(const float4*)&As[cur][kk][ty*8+4];
            *(float4*)&b[0] = *(const float4*)&Bs[cur][kk][tx*8];
            *(float4*)&b[4] = *(const float4*)&Bs[cur][kk][tx*8+4];
            #pragma unroll
            for (int i=0;i<8;i++)
                #pragma unroll
                for (int j=0;j<8;j++) acc[i][j] = fmaf(a[i], b[j], acc[i][j]);
        }
        if (t + 1 < nk) {
            const int nxt = cur ^ 1;
            As[nxt][a_k+0][a_m]=af.x; As[nxt][a_k+1][a_m]=af.y;
            As[nxt][a_k+2][a_m]=af.z; As[nxt][a_k+3][a_m]=af.w;
            Bs[nxt][a_k+0][a_m]=bf.x; Bs[nxt][a_k+1][a_m]=bf.y;
            Bs[nxt][a_k+2][a_m]=bf.z; Bs[nxt][a_k+3][a_m]=bf.w;
            __syncthreads();
        }
    }

    const float alpha = 0.125f;
    #pragma unroll
    for (int i=0;i<8;i++) {
        int gm = m0 + ty*8 + i;
        if (gm < Nn) {
            int gn = n0 + tx*8;
            float* cp = Cs + (size_t)gm*SLD + gn;
            if (gn + 7 < Nn) {
                float4 v0, v1;
                v0.x=acc[i][0]*alpha; v0.y=acc[i][1]*alpha; v0.z=acc[i][2]*alpha; v0.w=acc[i][3]*alpha;
                v1.x=acc[i][4]*alpha; v1.y=acc[i][5]*alpha; v1.z=acc[i][6]*alpha; v1.w=acc[i][7]*alpha;
                *(float4*)cp = v0; *(float4*)(cp+4) = v1;
            } else {
                #pragma unroll
                for (int j=0;j<8;j++) if (gn + j < Nn) cp[j] = acc[i][j]*alpha;
            }
        }
    }
}

// ---------------- row softmax over N=1025 (stride SLD) ----------------
__global__ __launch_bounds__(256)
void softmax_kernel(float* __restrict__ S)
{
    const int r = blockIdx.x;
    float* row = S + (size_t)(r / Nn) * SB + (size_t)(r % Nn) * SLD;
    __shared__ float red[256];
    const int t = threadIdx.x;

    float mx = -INFINITY;
    for (int j = t; j < Nn; j += 256) mx = fmaxf(mx, row[j]);
    red[t] = mx; __syncthreads();
    for (int s = 128; s > 0; s >>= 1) { if (t < s) red[t] = fmaxf(red[t], red[t+s]); __syncthreads(); }
    mx = red[0]; __syncthreads();

    float sm = 0.f;
    for (int j = t; j < Nn; j += 256) { float e = expf(row[j] - mx); row[j] = e; sm += e; }
    red[t] = sm; __syncthreads();
    for (int s = 128; s > 0; s >>= 1) { if (t < s) red[t] += red[t+s]; __syncthreads(); }
    const float inv = 1.f / red[0];
    for (int j = t; j < Nn; j += 256) row[j] *= inv;
}

// ---------------- zero small scratch ----------------
__global__ void zero_scratch_kernel()
{
    int idx = blockIdx.x * 256 + threadIdx.x;
    if (idx < BH*Nn) g_patch[idx] = 0.f;
    if (idx < Bsz*Nn) g_keep[idx] = 0.f;
    if (idx < Nn) g_cnt[idx] = 0.f;
}

// ---------------- column sums of attn per (b,h) ----------------
__global__ __launch_bounds__(256)
void colsum_kernel(const float* __restrict__ S)
{
    const int bh = blockIdx.x;
    const int i0 = blockIdx.y * 129;
    const int i1 = min(i0 + 129, Nn);
    const float* Sb = S + (size_t)bh * SB;
    const int t = threadIdx.x;

    float acc[5] = {0.f,0.f,0.f,0.f,0.f};
    for (int i = i0; i < i1; i++) {
        const float* row = Sb + (size_t)i * SLD;
        #pragma unroll
        for (int r = 0; r < 5; r++) { int j = t + 256*r; if (j < Nn) acc[r] += row[j]; }
    }
    #pragma unroll
    for (int r = 0; r < 5; r++) { int j = t + 256*r; if (j < Nn) atomicAdd(&g_patch[bh*Nn + j], acc[r]); }
}

// ---------------- combine patch means + exploration -> global_ucb ----------------
__global__ __launch_bounds__(256)
void ucb_combine_kernel(const float* __restrict__ ucb_score, const int* __restrict__ counter)
{
    const int b = blockIdx.x, t = threadIdx.x;
    const float logc = logf((float)(*counter) + 1.0f);
    for (int jj = t; jj < Nn-1; jj += 256) {
        int j = jj + 1;
        float s = 0.f;
        #pragma unroll
        for (int h = 0; h < Hh; h++) {
            float expl = sqrtf(logc / (ucb_score[h*Nn + j] + 1e-6f));
            s += g_patch[(b*Hh + h)*Nn + j] * (1.f/(float)Nn) + expl;
        }
        g_gucb[b*(Nn-1) + jj] = s * (1.f/(float)Hh);
    }
}

// ---------------- exact top-k via bitonic sort (ties -> lower index) ----------------
__global__ __launch_bounds__(512)
void topk_kernel()
{
    __shared__ float sv[1024];
    __shared__ int   si[1024];
    const int b = blockIdx.x, t = threadIdx.x;

    for (int j = t; j < 1024; j += 512) { sv[j] = g_gucb[b*1024 + j]; si[j] = j; }
    __syncthreads();

    for (int k = 2; k <= 1024; k <<= 1) {
        for (int j = k >> 1; j > 0; j >>= 1) {
            for (int i = t; i < 1024; i += 512) {
                int ixj = i ^ j;
                if (ixj > i) {
                    float v1 = sv[i], v2 = sv[ixj];
                    int  i1 = si[i],  i2 = si[ixj];
                    bool before = (v1 > v2) || (v1 == v2 && i1 < i2);
                    bool dirDesc = ((i & k) == 0);
                    bool doSwap = dirDesc ? (!before) : before;
                    if (doSwap) { sv[i] = v2; sv[ixj] = v1; si[i] = i2; si[ixj] = i1; }
                }
            }
            __syncthreads();
        }
    }

    if (t < KSEL) {
        int tok = si[t] + 1;
        g_keep[b*Nn + tok] = 1.f;
        atomicAdd(&g_cnt[tok], 1.f);
    }
    if (t == 0) g_keep[b*Nn + 0] = 1.f;
}

// =====================================================================
// gemm_ctx: fused prune-mask + renormalize + (pruned @ V).
// ctx[b,i,h*Dh+d] = (1/Z_i) * sum_j S[i,j]*f(i,j) * V[j,d]
//   f(i,j) = prune ? (keep[i] ? 1 : keep[j]) : 1
//   Z_i    = prune ? (sum_j S[i,j]*f(i,j) + 1e-8) : 1
// Tile: 128(m) x 64(n), BK=8, micro 4x8 (256 threads), double buffered.
// =====================================================================
__global__ __launch_bounds__(256)
void gemm_ctx(const float* __restrict__ S, const float* __restrict__ QKV,
              float* __restrict__ ctx, const int* __restrict__ counter,
              const int* __restrict__ enabled)
{
    const int bh = blockIdx.z;
    const int b = bh / Hh, h = bh % Hh;
    const bool prune = ((*enabled) != 0) && ((*counter) > 50);
    const float* Sp = S + (size_t)bh * SB;
    const float* V  = QKV + (size_t)b*Nn*3*Cc + 2*(size_t)Cc + (size_t)h*Dh;
    const float* kp = g_keep + b*Nn;
    float* Cp = ctx + (size_t)b*Nn*Cc + (size_t)h*Dh;

    __shared__ float As[2][8][132];
    __shared__ float Bs[2][8][64];
    __shared__ float zsh[128];

    const int tid = threadIdx.x;
    const int m0 = blockIdx.y * 128;
    const int a_m = tid >> 1, a_k = (tid & 1) << 2;
    const int gm_a = m0 + a_m;
    const bool a_ok = gm_a < Nn;
    const float keepI = (a_ok && prune) ? kp[gm_a] : 1.f;
    const float* Ap = Sp + (size_t)(a_ok ? gm_a : 0) * SLD;
    const int b_k = tid >> 4, b_n = (tid & 15) << 2;     // valid for tid<128
    const float* Bp = V + (size_t)b_k * (3*Cc) + b_n;

    // ---- A tile loader: masked S values ----
    auto loadA = [&](int k0) -> float4 {
        float4 v = make_float4(0.f,0.f,0.f,0.f);
        if (a_ok) {
            int k = k0 + a_k;
            if (k + 3 < Nn) v = *(const float4*)(Ap + k);
            else {
                if (k+0 < Nn) v.x = Ap[k+0];
                if (k+1 < Nn) v.y = Ap[k+1];
                if (k+2 < Nn) v.z = Ap[k+2];
                if (k+3 < Nn) v.w = Ap[k+3];
            }
            if (keepI < 0.5f) {   // implies prune==true
                v.x *= kp[min(k+0, Nn-1)];
                v.y *= kp[min(k+1, Nn-1)];
                v.z *= kp[min(k+2, Nn-1)];
                v.w *= kp[min(k+3, Nn-1)];
            }
        }
        return v;
    };
    auto loadB = [&](int k0) -> float4 {
        float4 v = make_float4(0.f,0.f,0.f,0.f);
        if (tid < 128 && (k0 + b_k) < Nn) v = *(const float4*)(Bp + (size_t)k0 * (3*Cc));
        return v;
    };

    float4 af = loadA(0);
    float4 bf = loadB(0);
    As[0][a_k+0][a_m]=af.x; As[0][a_k+1][a_m]=af.y;
    As[0][a_k+2][a_m]=af.z; As[0][a_k+3][a_m]=af.w;
    if (tid < 128) *(float4*)&Bs[0][b_k][b_n] = bf;
    __syncthreads();

    const int tx = tid & 7, ty = tid >> 3;   // tx: 8 col-groups of 8; ty: 32 row-groups of 4
    float acc[4][8];
    #pragma unroll
    for (int i=0;i<4;i++)
        #pragma unroll
        for (int j=0;j<8;j++) acc[i][j]=0.f;
    float zacc[4] = {0.f,0.f,0.f,0.f};

    const int nk = (Nn + 7) >> 3;   // 129
    for (int t = 0; t < nk; t++) {
        const int cur = t & 1;
        if (t + 1 < nk) { af = loadA((t+1)*8); bf = loadB((t+1)*8); }
        #pragma unroll
        for (int kk = 0; kk < 8; kk++) {
            float a[4], bb[8];
            *(float4*)&a[0]  = *(const float4*)&As[cur][kk][ty*4];
            *(float4*)&bb[0] = *(const float4*)&Bs[cur][kk][tx*8];
            *(float4*)&bb[4] = *(const float4*)&Bs[cur][kk][tx*8+4];
            #pragma unroll
            for (int i=0;i<4;i++)
                #pragma unroll
                for (int j=0;j<8;j++) acc[i][j] = fmaf(a[i], bb[j], acc[i][j]);
            if (tx == 0) {
                #pragma unroll
                for (int i=0;i<4;i++) zacc[i] += a[i];
            }
        }
        if (t + 1 < nk) {
            const int nxt = cur ^ 1;
            As[nxt][a_k+0][a_m]=af.x; As[nxt][a_k+1][a_m]=af.y;
            As[nxt][a_k+2][a_m]=af.z; As[nxt][a_k+3][a_m]=af.w;
            if (tid < 128) *(float4*)&Bs[nxt][b_k][b_n] = bf;
            __syncthreads();
        }
    }

    if (tx == 0) {
        #pragma unroll
        for (int i=0;i<4;i++) zsh[ty*4+i] = zacc[i];
    }
    __syncthreads();

    #pragma unroll
    for (int i=0;i<4;i++) {
        int gm = m0 + ty*4 + i;
        if (gm < Nn) {
            float invZ = prune ? (1.f / (zsh[ty*4+i] + 1e-8f)) : 1.f;
            float* cp = Cp + (size_t)gm * Cc + tx*8;
            float4 v0, v1;
            v0.x=acc[i][0]*invZ; v0.y=acc[i][1]*invZ; v0.z=acc[i][2]*invZ; v0.w=acc[i][3]*invZ;
            v1.x=acc[i][4]*invZ; v1.y=acc[i][5]*invZ; v1.z=acc[i][6]*invZ; v1.w=acc[i][7]*invZ;
            *(float4*)cp = v0; *(float4*)(cp+4) = v1;
        }
    }
}

// ---------------- score_delta = broadcast(cnt / B) to [H,N] ----------------
__global__ void score_delta_kernel(float* __restrict__ out2)
{
    int idx = blockIdx.x * 256 + threadIdx.x;
    if (idx < Hh*Nn) out2[idx] = g_cnt[idx % Nn] * (1.f / (float)Bsz);
}

// =======================================================================
extern "C" void kernel_launch(void* const* d_in, const int* in_sizes, int n_in,
                              void* d_out, int out_size)
{
    const float* x       = (const float*)d_in[0];
    const float* ucbsc   = (const float*)d_in[1];
    const float* Wqkv    = (const float*)d_in[2];
    const float* Wproj   = (const float*)d_in[3];
    const float* bproj   = (const float*)d_in[4];
    const int*   counter = (const int*)d_in[5];
    const int*   enabled = (const int*)d_in[6];
    float* out = (float*)d_out;

    float *qkv, *S, *ctx;
    cudaGetSymbolAddress((void**)&qkv, g_qkv);
    cudaGetSymbolAddress((void**)&S,   g_S);
    cudaGetSymbolAddress((void**)&ctx, g_ctx);

    // 1) qkv = x @ W_qkv    [4100 x 2304 x 768]
    {
        dim3 grid(2304/128, (Bsz*Nn + 127)/128);
        gemm_nn<false><<<grid, 256>>>(x, Wqkv, nullptr, qkv,
                                      Bsz*Nn, 3*Cc, Cc, Cc, 3*Cc, 3*Cc);
    }
    // 2) S = 0.125 * Q @ K^T per (b,h)
    {
        dim3 grid((Nn+127)/128, (Nn+127)/128, BH);
        gemm_qk<<<grid, 256>>>(qkv, S);
    }
    // 3) softmax rows
    softmax_kernel<<<BH*Nn, 256>>>(S);

    // 4) scratch zero, column sums, ucb combine, top-k
    zero_scratch_kernel<<<(BH*Nn + 255)/256, 256>>>();
    { dim3 grid(BH, 8); colsum_kernel<<<grid, 256>>>(S); }
    ucb_combine_kernel<<<Bsz, 256>>>(ucbsc, counter);
    topk_kernel<<<Bsz, 512>>>();

    // 5) fused prune+renorm+context GEMM
    {
        dim3 grid(1, (Nn+127)/128, BH);
        gemm_ctx<<<grid, 256>>>(S, qkv, ctx, counter, enabled);
    }
    // 6) out = ctx @ W_proj + b_proj   [4100 x 768 x 768]
    {
        dim3 grid(768/128, (Bsz*Nn + 127)/128);
        gemm_nn<true><<<grid, 256>>>(ctx, Wproj, bproj, out,
                                     Bsz*Nn, Cc, Cc, Cc, Cc, Cc);
    }
    // 7) score_delta
    if (out_size >= Bsz*Nn*Cc + Hh*Nn) {
        score_delta_kernel<<<(Hh*Nn + 255)/256, 256>>>(out + (size_t)Bsz*Nn*Cc);
    }
}

// round 4
// speedup vs baseline: 2.6111x; 1.9270x over previous
#include <cuda_runtime.h>
#include <math.h>
#include <stdint.h>

// ---------------- problem constants ----------------
#define Bsz 4
#define Nn  1025
#define Cc  768
#define Hh  12
#define Dh  64
#define BH  (Bsz*Hh)           // 48
#define SLD 1028               // padded row stride for S
#define KLD 1028               // padded row stride for keep mask (16B-aligned rows)
#define SB  ((size_t)Nn*SLD)
#define KSEL 256

// ---------------- scratch (device globals; allocs forbidden) ----------------
__device__ float g_qkv[(size_t)Bsz*Nn*3*Cc];
__device__ float g_S  [(size_t)BH*Nn*SLD];
__device__ float g_ctx[(size_t)Bsz*Nn*Cc];
__device__ float g_patch[BH*Nn];
__device__ float g_gucb[Bsz*(Nn-1)];
__device__ float g_keep[Bsz*KLD];
__device__ float g_cnt[Nn];

// ---------------- tf32 helpers ----------------
__device__ __forceinline__ uint32_t f2tf(float x){
    uint32_t r; asm("cvt.rna.tf32.f32 %0, %1;" : "=r"(r) : "f"(x)); return r;
}
__device__ __forceinline__ void mma8(float* d, const uint32_t* a, const uint32_t* b){
    asm volatile("mma.sync.aligned.m16n8k8.row.col.f32.tf32.tf32.f32 "
        "{%0,%1,%2,%3}, {%4,%5,%6,%7}, {%8,%9}, {%0,%1,%2,%3};"
        : "+f"(d[0]), "+f"(d[1]), "+f"(d[2]), "+f"(d[3])
        : "r"(a[0]), "r"(a[1]), "r"(a[2]), "r"(a[3]), "r"(b[0]), "r"(b[1]));
}

// =====================================================================
// mma_gemm_nn: C[M,N] = A[M,K] @ B[K,N] (+bias).  tf32 tensor cores.
// Block tile 128x128, BK=16, 8 warps (4m x 2n), warp tile 32m x 64n.
// =====================================================================
template<bool BIAS>
__global__ __launch_bounds__(256,1)
void mma_gemm_nn(const float* __restrict__ A, const float* __restrict__ B,
                 const float* __restrict__ bias, float* __restrict__ C,
                 int M, int N, int K, int lda, int ldb, int ldc)
{
    __shared__ uint32_t As[2][16][136];
    __shared__ uint32_t Bs[2][16][136];
    const int tid = threadIdx.x, lane = tid & 31, warp = tid >> 5;
    const int wm = warp & 3;
    const int wN = warp >> 2;                      // 0..1
    const int m0 = blockIdx.y*128, n0 = blockIdx.x*128;

    const int ar = tid >> 2, ak = (tid & 3) << 2;
    const bool aok0 = (m0 + ar)      < M;
    const bool aok1 = (m0 + ar + 64) < M;
    const float* Ap0 = A + (size_t)(m0+ar)*lda + ak;
    const float* Ap1 = A + (size_t)(m0+ar+64)*lda + ak;
    const int bk = tid >> 5, bn = (tid & 31) << 2;
    const float* Bp0 = B + (size_t)bk*ldb + n0 + bn;
    const float* Bp1 = B + (size_t)(bk+8)*ldb + n0 + bn;

    const float4 z4 = make_float4(0.f,0.f,0.f,0.f);
    float4 a0 = aok0 ? *(const float4*)Ap0 : z4;
    float4 a1 = aok1 ? *(const float4*)Ap1 : z4;
    float4 b0 = *(const float4*)Bp0;
    float4 b1 = *(const float4*)Bp1;

    auto stA = [&](int buf, const float4& v0, const float4& v1){
        As[buf][ak+0][ar]=f2tf(v0.x); As[buf][ak+1][ar]=f2tf(v0.y);
        As[buf][ak+2][ar]=f2tf(v0.z); As[buf][ak+3][ar]=f2tf(v0.w);
        As[buf][ak+0][ar+64]=f2tf(v1.x); As[buf][ak+1][ar+64]=f2tf(v1.y);
        As[buf][ak+2][ar+64]=f2tf(v1.z); As[buf][ak+3][ar+64]=f2tf(v1.w);
    };
    auto stB = [&](int buf, const float4& v0, const float4& v1){
        *(uint4*)&Bs[buf][bk  ][bn] = make_uint4(f2tf(v0.x),f2tf(v0.y),f2tf(v0.z),f2tf(v0.w));
        *(uint4*)&Bs[buf][bk+8][bn] = make_uint4(f2tf(v1.x),f2tf(v1.y),f2tf(v1.z),f2tf(v1.w));
    };

    stA(0,a0,a1); stB(0,b0,b1); __syncthreads();

    float acc[2][8][4];
    #pragma unroll
    for (int i=0;i<2;i++)
        #pragma unroll
        for (int j=0;j<8;j++)
            #pragma unroll
            for (int q=0;q<4;q++) acc[i][j][q]=0.f;

    const int nk = K >> 4;
    for (int t=0;t<nk;t++){
        const int cur = t & 1;
        if (t+1<nk){
            a0 = aok0 ? *(const float4*)(Ap0 + (t+1)*16) : z4;
            a1 = aok1 ? *(const float4*)(Ap1 + (t+1)*16) : z4;
            b0 = *(const float4*)(Bp0 + (size_t)(t+1)*16*ldb);
            b1 = *(const float4*)(Bp1 + (size_t)(t+1)*16*ldb);
        }
        #pragma unroll
        for (int ks=0;ks<2;ks++){
            const int kb = ks*8;
            uint32_t af[2][4], bf[8][2];
            #pragma unroll
            for (int mt=0;mt<2;mt++){
                const int r = wm*32 + mt*16 + (lane>>2);
                af[mt][0] = As[cur][kb+(lane&3)  ][r];
                af[mt][1] = As[cur][kb+(lane&3)  ][r+8];
                af[mt][2] = As[cur][kb+(lane&3)+4][r];
                af[mt][3] = As[cur][kb+(lane&3)+4][r+8];
            }
            #pragma unroll
            for (int nt=0;nt<8;nt++){
                const int c = wN*64 + nt*8 + (lane>>2);
                bf[nt][0] = Bs[cur][kb+(lane&3)  ][c];
                bf[nt][1] = Bs[cur][kb+(lane&3)+4][c];
            }
            #pragma unroll
            for (int mt=0;mt<2;mt++)
                #pragma unroll
                for (int nt=0;nt<8;nt++) mma8(acc[mt][nt], af[mt], bf[nt]);
        }
        if (t+1<nk){ const int nxt = cur^1; stA(nxt,a0,a1); stB(nxt,b0,b1); }
        __syncthreads();
    }

    #pragma unroll
    for (int mt=0;mt<2;mt++){
        const int r0 = m0 + wm*32 + mt*16 + (lane>>2);
        #pragma unroll
        for (int nt=0;nt<8;nt++){
            const int gc = n0 + wN*64 + nt*8 + (lane&3)*2;
            float bx=0.f, by=0.f;
            if (BIAS){ bx = bias[gc]; by = bias[gc+1]; }
            if (r0 < M){
                float2 v; v.x = acc[mt][nt][0]+bx; v.y = acc[mt][nt][1]+by;
                *(float2*)&C[(size_t)r0*ldc + gc] = v;
            }
            if (r0+8 < M){
                float2 v; v.x = acc[mt][nt][2]+bx; v.y = acc[mt][nt][3]+by;
                *(float2*)&C[(size_t)(r0+8)*ldc + gc] = v;
            }
        }
    }
}

// =====================================================================
// mma_gemm_qk: S[bh] = 0.125 * Q @ K^T.  Operand rows stride 3*Cc.
// =====================================================================
__global__ __launch_bounds__(256,1)
void mma_gemm_qk(const float* __restrict__ QKV, float* __restrict__ S)
{
    const int bh = blockIdx.z, b = bh / Hh, h = bh % Hh;
    const float* Q  = QKV + (size_t)b*Nn*3*Cc + (size_t)h*Dh;
    const float* Km = Q + Cc;
    float* Cs = S + (size_t)bh * SB;

    __shared__ uint32_t As[2][16][136];
    __shared__ uint32_t Bs[2][16][136];
    const int tid = threadIdx.x, lane = tid & 31, warp = tid >> 5;
    const int wm = warp & 3, wN = warp >> 2;
    const int m0 = blockIdx.y*128, n0 = blockIdx.x*128;

    const int ar = tid >> 2, ak = (tid & 3) << 2;
    const bool aok0 = (m0 + ar)      < Nn;
    const bool aok1 = (m0 + ar + 64) < Nn;
    const bool bok0 = (n0 + ar)      < Nn;
    const bool bok1 = (n0 + ar + 64) < Nn;
    const float* Ap0 = Q  + (size_t)(m0+ar)*(3*Cc) + ak;
    const float* Ap1 = Q  + (size_t)(m0+ar+64)*(3*Cc) + ak;
    const float* Bp0 = Km + (size_t)(n0+ar)*(3*Cc) + ak;
    const float* Bp1 = Km + (size_t)(n0+ar+64)*(3*Cc) + ak;

    const float4 z4 = make_float4(0.f,0.f,0.f,0.f);
    float4 a0 = aok0 ? *(const float4*)Ap0 : z4;
    float4 a1 = aok1 ? *(const float4*)Ap1 : z4;
    float4 b0 = bok0 ? *(const float4*)Bp0 : z4;
    float4 b1 = bok1 ? *(const float4*)Bp1 : z4;

    auto stT = [&](uint32_t (*dst)[136], const float4& v0, const float4& v1){
        dst[ak+0][ar]=f2tf(v0.x); dst[ak+1][ar]=f2tf(v0.y);
        dst[ak+2][ar]=f2tf(v0.z); dst[ak+3][ar]=f2tf(v0.w);
        dst[ak+0][ar+64]=f2tf(v1.x); dst[ak+1][ar+64]=f2tf(v1.y);
        dst[ak+2][ar+64]=f2tf(v1.z); dst[ak+3][ar+64]=f2tf(v1.w);
    };

    stT(As[0],a0,a1); stT(Bs[0],b0,b1); __syncthreads();

    float acc[2][8][4];
    #pragma unroll
    for (int i=0;i<2;i++)
        #pragma unroll
        for (int j=0;j<8;j++)
            #pragma unroll
            for (int q=0;q<4;q++) acc[i][j][q]=0.f;

    const int nk = Dh >> 4;   // 4
    for (int t=0;t<nk;t++){
        const int cur = t & 1;
        if (t+1<nk){
            a0 = aok0 ? *(const float4*)(Ap0 + (t+1)*16) : z4;
            a1 = aok1 ? *(const float4*)(Ap1 + (t+1)*16) : z4;
            b0 = bok0 ? *(const float4*)(Bp0 + (t+1)*16) : z4;
            b1 = bok1 ? *(const float4*)(Bp1 + (t+1)*16) : z4;
        }
        #pragma unroll
        for (int ks=0;ks<2;ks++){
            const int kb = ks*8;
            uint32_t af[2][4], bf[8][2];
            #pragma unroll
            for (int mt=0;mt<2;mt++){
                const int r = wm*32 + mt*16 + (lane>>2);
                af[mt][0] = As[cur][kb+(lane&3)  ][r];
                af[mt][1] = As[cur][kb+(lane&3)  ][r+8];
                af[mt][2] = As[cur][kb+(lane&3)+4][r];
                af[mt][3] = As[cur][kb+(lane&3)+4][r+8];
            }
            #pragma unroll
            for (int nt=0;nt<8;nt++){
                const int c = wN*64 + nt*8 + (lane>>2);
                bf[nt][0] = Bs[cur][kb+(lane&3)  ][c];
                bf[nt][1] = Bs[cur][kb+(lane&3)+4][c];
            }
            #pragma unroll
            for (int mt=0;mt<2;mt++)
                #pragma unroll
                for (int nt=0;nt<8;nt++) mma8(acc[mt][nt], af[mt], bf[nt]);
        }
        if (t+1<nk){ const int nxt = cur^1; stT(As[nxt],a0,a1); stT(Bs[nxt],b0,b1); }
        __syncthreads();
    }

    const float alpha = 0.125f;
    #pragma unroll
    for (int mt=0;mt<2;mt++){
        const int r0 = m0 + wm*32 + mt*16 + (lane>>2);
        #pragma unroll
        for (int nt=0;nt<8;nt++){
            const int gc = n0 + wN*64 + nt*8 + (lane&3)*2;
            if (r0 < Nn){
                if (gc+1 < Nn){
                    float2 v; v.x=acc[mt][nt][0]*alpha; v.y=acc[mt][nt][1]*alpha;
                    *(float2*)&Cs[(size_t)r0*SLD + gc] = v;
                } else if (gc < Nn) Cs[(size_t)r0*SLD + gc] = acc[mt][nt][0]*alpha;
            }
            if (r0+8 < Nn){
                if (gc+1 < Nn){
                    float2 v; v.x=acc[mt][nt][2]*alpha; v.y=acc[mt][nt][3]*alpha;
                    *(float2*)&Cs[(size_t)(r0+8)*SLD + gc] = v;
                } else if (gc < Nn) Cs[(size_t)(r0+8)*SLD + gc] = acc[mt][nt][2]*alpha;
            }
        }
    }
}

// =====================================================================
// mma_gemm_ctx: fused prune-mask + renorm + (pruned @ V).
// =====================================================================
__global__ __launch_bounds__(256,1)
void mma_gemm_ctx(const float* __restrict__ S, const float* __restrict__ QKV,
                  float* __restrict__ ctx, const int* __restrict__ counter,
                  const int* __restrict__ enabled)
{
    const int bh = blockIdx.z, b = bh / Hh, h = bh % Hh;
    const bool prune = ((*enabled) != 0) && ((*counter) > 50);
    const float* Sp = S + (size_t)bh*SB;
    const float* V  = QKV + (size_t)b*Nn*3*Cc + 2*(size_t)Cc + (size_t)h*Dh;
    const float* kp = g_keep + (size_t)b*KLD;   // 16B-aligned rows
    float* Cp = ctx + (size_t)b*Nn*Cc + (size_t)h*Dh;

    __shared__ uint32_t As[2][16][136];
    __shared__ uint32_t Bs[2][16][72];
    __shared__ float zsh[128];

    const int tid = threadIdx.x, lane = tid & 31, warp = tid >> 5;
    const int wm = warp & 3, wN = warp >> 2;
    const int m0 = blockIdx.y*128;

    const int ar = tid >> 2, ak = (tid & 3) << 2;
    const int gm0 = m0 + ar, gm1 = m0 + ar + 64;
    const bool aok0 = gm0 < Nn, aok1 = gm1 < Nn;
    const float keep0 = (prune && aok0) ? kp[gm0] : 1.f;
    const float keep1 = (prune && aok1) ? kp[gm1] : 1.f;
    const float* Ap0 = Sp + (size_t)(aok0 ? gm0 : 0)*SLD;
    const float* Ap1 = Sp + (size_t)(aok1 ? gm1 : 0)*SLD;
    const int bk = tid >> 4, bn = (tid & 15) << 2;
    const float* Bp = V + (size_t)bk*(3*Cc) + bn;

    const float4 z4 = make_float4(0.f,0.f,0.f,0.f);
    float z0 = 0.f, z1 = 0.f;

    auto ldrow = [&](const float* rowp, float keepi, int k0, bool ok, float& zacc)->float4{
        float4 v = z4;
        if (ok){
            const int c = k0 + ak;
            if (c + 3 < Nn) v = *(const float4*)(rowp + c);
            else {
                if (c   < Nn) v.x = rowp[c];
                if (c+1 < Nn) v.y = rowp[c+1];
                if (c+2 < Nn) v.z = rowp[c+2];
                if (c+3 < Nn) v.w = rowp[c+3];
            }
            if (keepi < 0.5f){
                float4 kv = z4;
                if (c + 3 < Nn) kv = *(const float4*)(kp + c);   // kp rows 16B-aligned now
                else {
                    if (c   < Nn) kv.x = kp[c];
                    if (c+1 < Nn) kv.y = kp[c+1];
                    if (c+2 < Nn) kv.z = kp[c+2];
                    if (c+3 < Nn) kv.w = kp[c+3];
                }
                v.x*=kv.x; v.y*=kv.y; v.z*=kv.z; v.w*=kv.w;
            }
            zacc += (v.x+v.y)+(v.z+v.w);
        }
        return v;
    };
    auto ldB = [&](int k0)->float4{
        return (k0 + bk < Nn) ? *(const float4*)(Bp + (size_t)k0*(3*Cc)) : z4;
    };
    auto stA = [&](int buf, const float4& v0, const float4& v1){
        As[buf][ak+0][ar]=f2tf(v0.x); As[buf][ak+1][ar]=f2tf(v0.y);
        As[buf][ak+2][ar]=f2tf(v0.z); As[buf][ak+3][ar]=f2tf(v0.w);
        As[buf][ak+0][ar+64]=f2tf(v1.x); As[buf][ak+1][ar+64]=f2tf(v1.y);
        As[buf][ak+2][ar+64]=f2tf(v1.z); As[buf][ak+3][ar+64]=f2tf(v1.w);
    };
    auto stB = [&](int buf, const float4& v){
        *(uint4*)&Bs[buf][bk][bn] = make_uint4(f2tf(v.x),f2tf(v.y),f2tf(v.z),f2tf(v.w));
    };

    float4 a0 = ldrow(Ap0, keep0, 0, aok0, z0);
    float4 a1 = ldrow(Ap1, keep1, 0, aok1, z1);
    float4 bv = ldB(0);
    stA(0,a0,a1); stB(0,bv); __syncthreads();

    float acc[2][4][4];
    #pragma unroll
    for (int i=0;i<2;i++)
        #pragma unroll
        for (int j=0;j<4;j++)
            #pragma unroll
            for (int q=0;q<4;q++) acc[i][j][q]=0.f;

    const int nk = (Nn + 15) >> 4;   // 65
    for (int t=0;t<nk;t++){
        const int cur = t & 1;
        if (t+1<nk){
            a0 = ldrow(Ap0, keep0, (t+1)*16, aok0, z0);
            a1 = ldrow(Ap1, keep1, (t+1)*16, aok1, z1);
            bv = ldB((t+1)*16);
        }
        #pragma unroll
        for (int ks=0;ks<2;ks++){
            const int kb = ks*8;
            uint32_t af[2][4], bf[4][2];
            #pragma unroll
            for (int mt=0;mt<2;mt++){
                const int r = wm*32 + mt*16 + (lane>>2);
                af[mt][0] = As[cur][kb+(lane&3)  ][r];
                af[mt][1] = As[cur][kb+(lane&3)  ][r+8];
                af[mt][2] = As[cur][kb+(lane&3)+4][r];
                af[mt][3] = As[cur][kb+(lane&3)+4][r+8];
            }
            #pragma unroll
            for (int nt=0;nt<4;nt++){
                const int c = wN*32 + nt*8 + (lane>>2);
                bf[nt][0] = Bs[cur][kb+(lane&3)  ][c];
                bf[nt][1] = Bs[cur][kb+(lane&3)+4][c];
            }
            #pragma unroll
            for (int mt=0;mt<2;mt++)
                #pragma unroll
                for (int nt=0;nt<4;nt++) mma8(acc[mt][nt], af[mt], bf[nt]);
        }
        if (t+1<nk){ const int nxt = cur^1; stA(nxt,a0,a1); stB(nxt,bv); }
        __syncthreads();
    }

    z0 += __shfl_xor_sync(0xffffffffu, z0, 1);
    z0 += __shfl_xor_sync(0xffffffffu, z0, 2);
    z1 += __shfl_xor_sync(0xffffffffu, z1, 1);
    z1 += __shfl_xor_sync(0xffffffffu, z1, 2);
    if ((lane & 3) == 0){ zsh[ar] = z0; zsh[ar+64] = z1; }
    __syncthreads();

    #pragma unroll
    for (int mt=0;mt<2;mt++){
        const int lr = wm*32 + mt*16 + (lane>>2);
        const int r0 = m0 + lr;
        const float iz0 = prune ? 1.f/(zsh[lr]   + 1e-8f) : 1.f;
        const float iz1 = prune ? 1.f/(zsh[lr+8] + 1e-8f) : 1.f;
        #pragma unroll
        for (int nt=0;nt<4;nt++){
            const int gc = wN*32 + nt*8 + (lane&3)*2;
            if (r0 < Nn){
                float2 v; v.x=acc[mt][nt][0]*iz0; v.y=acc[mt][nt][1]*iz0;
                *(float2*)&Cp[(size_t)r0*Cc + gc] = v;
            }
            if (r0+8 < Nn){
                float2 v; v.x=acc[mt][nt][2]*iz1; v.y=acc[mt][nt][3]*iz1;
                *(float2*)&Cp[(size_t)(r0+8)*Cc + gc] = v;
            }
        }
    }
}

// ---------------- row softmax (vectorized) ----------------
__global__ __launch_bounds__(256)
void softmax_kernel(float* __restrict__ S)
{
    const int r = blockIdx.x;
    float* row = S + (size_t)(r / Nn)*SB + (size_t)(r % Nn)*SLD;
    const int t = threadIdx.x;
    __shared__ float red[256];

    float4 v = ((const float4*)row)[t];
    const float last = row[1024];
    float mx = fmaxf(fmaxf(v.x,v.y), fmaxf(v.z,v.w));
    mx = fmaxf(mx, last);
    red[t] = mx; __syncthreads();
    for (int s=128;s>0;s>>=1){ if (t<s) red[t]=fmaxf(red[t],red[t+s]); __syncthreads(); }
    mx = red[0]; __syncthreads();

    float4 e;
    e.x = __expf(v.x-mx); e.y = __expf(v.y-mx);
    e.z = __expf(v.z-mx); e.w = __expf(v.w-mx);
    const float el = __expf(last-mx);
    float sm = (e.x+e.y)+(e.z+e.w);
    if (t==0) sm += el;
    red[t] = sm; __syncthreads();
    for (int s=128;s>0;s>>=1){ if (t<s) red[t]+=red[t+s]; __syncthreads(); }
    const float inv = 1.f/red[0];
    e.x*=inv; e.y*=inv; e.z*=inv; e.w*=inv;
    ((float4*)row)[t] = e;
    if (t==0) row[1024] = el*inv;
}

// ---------------- zero small scratch ----------------
__global__ void zero_scratch_kernel()
{
    int idx = blockIdx.x*256 + threadIdx.x;
    if (idx < BH*Nn) g_patch[idx] = 0.f;
    if (idx < Bsz*KLD) g_keep[idx] = 0.f;
    if (idx < Nn) g_cnt[idx] = 0.f;
}

// ---------------- column sums per (b,h) ----------------
__global__ __launch_bounds__(256)
void colsum_kernel(const float* __restrict__ S)
{
    const int bh = blockIdx.x;
    const int i0 = blockIdx.y*129, i1 = min(i0+129, Nn);
    const float* Sb = S + (size_t)bh*SB;
    const int t = threadIdx.x;

    float4 acc = make_float4(0.f,0.f,0.f,0.f);
    float accl = 0.f;
    for (int i=i0;i<i1;i++){
        const float* row = Sb + (size_t)i*SLD;
        const float4 v = ((const float4*)row)[t];
        acc.x+=v.x; acc.y+=v.y; acc.z+=v.z; acc.w+=v.w;
        if (t==0) accl += row[1024];
    }
    float* base = &g_patch[bh*Nn];
    atomicAdd(&base[t*4+0], acc.x);
    atomicAdd(&base[t*4+1], acc.y);
    atomicAdd(&base[t*4+2], acc.z);
    atomicAdd(&base[t*4+3], acc.w);
    if (t==0) atomicAdd(&base[1024], accl);
}

// ---------------- combine patch means + exploration ----------------
__global__ __launch_bounds__(256)
void ucb_combine_kernel(const float* __restrict__ ucb_score, const int* __restrict__ counter)
{
    const int b = blockIdx.x, t = threadIdx.x;
    const float logc = logf((float)(*counter) + 1.0f);
    for (int jj=t; jj<Nn-1; jj+=256){
        const int j = jj + 1;
        float s = 0.f;
        #pragma unroll
        for (int h=0; h<Hh; h++){
            const float expl = sqrtf(logc / (ucb_score[h*Nn + j] + 1e-6f));
            s += g_patch[(b*Hh + h)*Nn + j] * (1.f/(float)Nn) + expl;
        }
        g_gucb[b*(Nn-1) + jj] = s * (1.f/(float)Hh);
    }
}

// ---------------- exact top-k (bitonic; ties -> lower index) ----------------
__global__ __launch_bounds__(512)
void topk_kernel()
{
    __shared__ float sv[1024];
    __shared__ int   si[1024];
    const int b = blockIdx.x, t = threadIdx.x;

    for (int j=t;j<1024;j+=512){ sv[j] = g_gucb[b*1024 + j]; si[j] = j; }
    __syncthreads();

    for (int k=2;k<=1024;k<<=1){
        for (int j=k>>1;j>0;j>>=1){
            for (int i=t;i<1024;i+=512){
                const int ixj = i ^ j;
                if (ixj > i){
                    float v1 = sv[i], v2 = sv[ixj];
                    int  i1 = si[i],  i2 = si[ixj];
                    const bool before = (v1 > v2) || (v1 == v2 && i1 < i2);
                    const bool dirDesc = ((i & k) == 0);
                    if (dirDesc ? (!before) : before){
                        sv[i]=v2; sv[ixj]=v1; si[i]=i2; si[ixj]=i1;
                    }
                }
            }
            __syncthreads();
        }
    }

    if (t < KSEL){
        const int tok = si[t] + 1;
        g_keep[b*KLD + tok] = 1.f;
        atomicAdd(&g_cnt[tok], 1.f);
    }
    if (t == 0) g_keep[b*KLD + 0] = 1.f;
}

// ---------------- score_delta ----------------
__global__ void score_delta_kernel(float* __restrict__ out2)
{
    int idx = blockIdx.x*256 + threadIdx.x;
    if (idx < Hh*Nn) out2[idx] = g_cnt[idx % Nn] * (1.f/(float)Bsz);
}

// =======================================================================
extern "C" void kernel_launch(void* const* d_in, const int* in_sizes, int n_in,
                              void* d_out, int out_size)
{
    const float* x       = (const float*)d_in[0];
    const float* ucbsc   = (const float*)d_in[1];
    const float* Wqkv    = (const float*)d_in[2];
    const float* Wproj   = (const float*)d_in[3];
    const float* bproj   = (const float*)d_in[4];
    const int*   counter = (const int*)d_in[5];
    const int*   enabled = (const int*)d_in[6];
    float* out = (float*)d_out;

    float *qkv, *S, *ctx;
    cudaGetSymbolAddress((void**)&qkv, g_qkv);
    cudaGetSymbolAddress((void**)&S,   g_S);
    cudaGetSymbolAddress((void**)&ctx, g_ctx);

    // 0) zero scratch (independent)
    zero_scratch_kernel<<<(BH*Nn + 255)/256, 256>>>();

    // 1) qkv = x @ W_qkv   [4100 x 2304 x 768]
    {
        dim3 grid(2304/128, (Bsz*Nn + 127)/128);
        mma_gemm_nn<false><<<grid, 256>>>(x, Wqkv, nullptr, qkv,
                                          Bsz*Nn, 3*Cc, Cc, Cc, 3*Cc, 3*Cc);
    }
    // 2) S = 0.125 * Q @ K^T  per (b,h)
    {
        dim3 grid((Nn+127)/128, (Nn+127)/128, BH);
        mma_gemm_qk<<<grid, 256>>>(qkv, S);
    }
    // 3) softmax rows
    softmax_kernel<<<BH*Nn, 256>>>(S);

    // 4) column sums, ucb combine, top-k
    { dim3 grid(BH, 8); colsum_kernel<<<grid, 256>>>(S); }
    ucb_combine_kernel<<<Bsz, 256>>>(ucbsc, counter);
    topk_kernel<<<Bsz, 512>>>();

    // 5) fused prune+renorm+context GEMM
    {
        dim3 grid(1, (Nn+127)/128, BH);
        mma_gemm_ctx<<<grid, 256>>>(S, qkv, ctx, counter, enabled);
    }
    // 6) out = ctx @ W_proj + b_proj
    {
        dim3 grid(768/128, (Bsz*Nn + 127)/128);
        mma_gemm_nn<true><<<grid, 256>>>(ctx, Wproj, bproj, out,
                                         Bsz*Nn, Cc, Cc, Cc, Cc, Cc);
    }
    // 7) score_delta
    if (out_size >= Bsz*Nn*Cc + Hh*Nn) {
        score_delta_kernel<<<(Hh*Nn + 255)/256, 256>>>(out + (size_t)Bsz*Nn*Cc);
    }
}

// round 5
// speedup vs baseline: 2.6124x; 1.0005x over previous
#include <cuda_runtime.h>
#include <math.h>
#include <stdint.h>

// ---------------- problem constants ----------------
#define Bsz 4
#define Nn  1025
#define Cc  768
#define Hh  12
#define Dh  64
#define BH  (Bsz*Hh)           // 48
#define SLD 1028               // padded row stride for S
#define KLD 1028               // padded row stride for keep mask (16B-aligned rows)
#define SB  ((size_t)Nn*SLD)
#define KSEL 256

// ---------------- scratch (device globals; allocs forbidden) ----------------
__device__ float g_qkv[(size_t)Bsz*Nn*3*Cc];
__device__ float g_S  [(size_t)BH*Nn*SLD];
__device__ float g_ctx[(size_t)Bsz*Nn*Cc];
__device__ float g_patch[BH*Nn];
__device__ float g_gucb[Bsz*(Nn-1)];
__device__ float g_keep[Bsz*KLD];
__device__ float g_cnt[Nn];

// ---------------- tf32 helpers ----------------
__device__ __forceinline__ uint32_t f2tf(float x){
    uint32_t r; asm("cvt.rna.tf32.f32 %0, %1;" : "=r"(r) : "f"(x)); return r;
}
__device__ __forceinline__ void mma8(float* d, const uint32_t* a, const uint32_t* b){
    asm volatile("mma.sync.aligned.m16n8k8.row.col.f32.tf32.tf32.f32 "
        "{%0,%1,%2,%3}, {%4,%5,%6,%7}, {%8,%9}, {%0,%1,%2,%3};"
        : "+f"(d[0]), "+f"(d[1]), "+f"(d[2]), "+f"(d[3])
        : "r"(a[0]), "r"(a[1]), "r"(a[2]), "r"(a[3]), "r"(b[0]), "r"(b[1]));
}

// =====================================================================
// mma_gemm_nn: C[M,N] = A[M,K] @ B[K,N] (+bias).  tf32 tensor cores.
// Block tile 128x128, BK=16, 8 warps (4m x 2n), warp tile 32m x 64n.
// =====================================================================
template<bool BIAS>
__global__ __launch_bounds__(256,1)
void mma_gemm_nn(const float* __restrict__ A, const float* __restrict__ B,
                 const float* __restrict__ bias, float* __restrict__ C,
                 int M, int N, int K, int lda, int ldb, int ldc)
{
    __shared__ uint32_t As[2][16][136];
    __shared__ uint32_t Bs[2][16][136];
    const int tid = threadIdx.x, lane = tid & 31, warp = tid >> 5;
    const int wm = warp & 3;
    const int wN = warp >> 2;                      // 0..1
    const int m0 = blockIdx.y*128, n0 = blockIdx.x*128;

    const int ar = tid >> 2, ak = (tid & 3) << 2;
    const bool aok0 = (m0 + ar)      < M;
    const bool aok1 = (m0 + ar + 64) < M;
    const float* Ap0 = A + (size_t)(m0+ar)*lda + ak;
    const float* Ap1 = A + (size_t)(m0+ar+64)*lda + ak;
    const int bk = tid >> 5, bn = (tid & 31) << 2;
    const float* Bp0 = B + (size_t)bk*ldb + n0 + bn;
    const float* Bp1 = B + (size_t)(bk+8)*ldb + n0 + bn;

    const float4 z4 = make_float4(0.f,0.f,0.f,0.f);
    float4 a0 = aok0 ? *(const float4*)Ap0 : z4;
    float4 a1 = aok1 ? *(const float4*)Ap1 : z4;
    float4 b0 = *(const float4*)Bp0;
    float4 b1 = *(const float4*)Bp1;

    auto stA = [&](int buf, const float4& v0, const float4& v1){
        As[buf][ak+0][ar]=f2tf(v0.x); As[buf][ak+1][ar]=f2tf(v0.y);
        As[buf][ak+2][ar]=f2tf(v0.z); As[buf][ak+3][ar]=f2tf(v0.w);
        As[buf][ak+0][ar+64]=f2tf(v1.x); As[buf][ak+1][ar+64]=f2tf(v1.y);
        As[buf][ak+2][ar+64]=f2tf(v1.z); As[buf][ak+3][ar+64]=f2tf(v1.w);
    };
    auto stB = [&](int buf, const float4& v0, const float4& v1){
        *(uint4*)&Bs[buf][bk  ][bn] = make_uint4(f2tf(v0.x),f2tf(v0.y),f2tf(v0.z),f2tf(v0.w));
        *(uint4*)&Bs[buf][bk+8][bn] = make_uint4(f2tf(v1.x),f2tf(v1.y),f2tf(v1.z),f2tf(v1.w));
    };

    stA(0,a0,a1); stB(0,b0,b1); __syncthreads();

    float acc[2][8][4];
    #pragma unroll
    for (int i=0;i<2;i++)
        #pragma unroll
        for (int j=0;j<8;j++)
            #pragma unroll
            for (int q=0;q<4;q++) acc[i][j][q]=0.f;

    const int nk = K >> 4;
    for (int t=0;t<nk;t++){
        const int cur = t & 1;
        if (t+1<nk){
            a0 = aok0 ? *(const float4*)(Ap0 + (t+1)*16) : z4;
            a1 = aok1 ? *(const float4*)(Ap1 + (t+1)*16) : z4;
            b0 = *(const float4*)(Bp0 + (size_t)(t+1)*16*ldb);
            b1 = *(const float4*)(Bp1 + (size_t)(t+1)*16*ldb);
        }
        #pragma unroll
        for (int ks=0;ks<2;ks++){
            const int kb = ks*8;
            uint32_t af[2][4], bf[8][2];
            #pragma unroll
            for (int mt=0;mt<2;mt++){
                const int r = wm*32 + mt*16 + (lane>>2);
                af[mt][0] = As[cur][kb+(lane&3)  ][r];
                af[mt][1] = As[cur][kb+(lane&3)  ][r+8];
                af[mt][2] = As[cur][kb+(lane&3)+4][r];
                af[mt][3] = As[cur][kb+(lane&3)+4][r+8];
            }
            #pragma unroll
            for (int nt=0;nt<8;nt++){
                const int c = wN*64 + nt*8 + (lane>>2);
                bf[nt][0] = Bs[cur][kb+(lane&3)  ][c];
                bf[nt][1] = Bs[cur][kb+(lane&3)+4][c];
            }
            #pragma unroll
            for (int mt=0;mt<2;mt++)
                #pragma unroll
                for (int nt=0;nt<8;nt++) mma8(acc[mt][nt], af[mt], bf[nt]);
        }
        if (t+1<nk){ const int nxt = cur^1; stA(nxt,a0,a1); stB(nxt,b0,b1); }
        __syncthreads();
    }

    #pragma unroll
    for (int mt=0;mt<2;mt++){
        const int r0 = m0 + wm*32 + mt*16 + (lane>>2);
        #pragma unroll
        for (int nt=0;nt<8;nt++){
            const int gc = n0 + wN*64 + nt*8 + (lane&3)*2;
            float bx=0.f, by=0.f;
            if (BIAS){ bx = bias[gc]; by = bias[gc+1]; }
            if (r0 < M){
                float2 v; v.x = acc[mt][nt][0]+bx; v.y = acc[mt][nt][1]+by;
                *(float2*)&C[(size_t)r0*ldc + gc] = v;
            }
            if (r0+8 < M){
                float2 v; v.x = acc[mt][nt][2]+bx; v.y = acc[mt][nt][3]+by;
                *(float2*)&C[(size_t)(r0+8)*ldc + gc] = v;
            }
        }
    }
}

// =====================================================================
// mma_gemm_qk: S[bh] = 0.125 * Q @ K^T.  Operand rows stride 3*Cc.
// =====================================================================
__global__ __launch_bounds__(256,1)
void mma_gemm_qk(const float* __restrict__ QKV, float* __restrict__ S)
{
    const int bh = blockIdx.z, b = bh / Hh, h = bh % Hh;
    const float* Q  = QKV + (size_t)b*Nn*3*Cc + (size_t)h*Dh;
    const float* Km = Q + Cc;
    float* Cs = S + (size_t)bh * SB;

    __shared__ uint32_t As[2][16][136];
    __shared__ uint32_t Bs[2][16][136];
    const int tid = threadIdx.x, lane = tid & 31, warp = tid >> 5;
    const int wm = warp & 3, wN = warp >> 2;
    const int m0 = blockIdx.y*128, n0 = blockIdx.x*128;

    const int ar = tid >> 2, ak = (tid & 3) << 2;
    const bool aok0 = (m0 + ar)      < Nn;
    const bool aok1 = (m0 + ar + 64) < Nn;
    const bool bok0 = (n0 + ar)      < Nn;
    const bool bok1 = (n0 + ar + 64) < Nn;
    const float* Ap0 = Q  + (size_t)(m0+ar)*(3*Cc) + ak;
    const float* Ap1 = Q  + (size_t)(m0+ar+64)*(3*Cc) + ak;
    const float* Bp0 = Km + (size_t)(n0+ar)*(3*Cc) + ak;
    const float* Bp1 = Km + (size_t)(n0+ar+64)*(3*Cc) + ak;

    const float4 z4 = make_float4(0.f,0.f,0.f,0.f);
    float4 a0 = aok0 ? *(const float4*)Ap0 : z4;
    float4 a1 = aok1 ? *(const float4*)Ap1 : z4;
    float4 b0 = bok0 ? *(const float4*)Bp0 : z4;
    float4 b1 = bok1 ? *(const float4*)Bp1 : z4;

    auto stT = [&](uint32_t (*dst)[136], const float4& v0, const float4& v1){
        dst[ak+0][ar]=f2tf(v0.x); dst[ak+1][ar]=f2tf(v0.y);
        dst[ak+2][ar]=f2tf(v0.z); dst[ak+3][ar]=f2tf(v0.w);
        dst[ak+0][ar+64]=f2tf(v1.x); dst[ak+1][ar+64]=f2tf(v1.y);
        dst[ak+2][ar+64]=f2tf(v1.z); dst[ak+3][ar+64]=f2tf(v1.w);
    };

    stT(As[0],a0,a1); stT(Bs[0],b0,b1); __syncthreads();

    float acc[2][8][4];
    #pragma unroll
    for (int i=0;i<2;i++)
        #pragma unroll
        for (int j=0;j<8;j++)
            #pragma unroll
            for (int q=0;q<4;q++) acc[i][j][q]=0.f;

    const int nk = Dh >> 4;   // 4
    for (int t=0;t<nk;t++){
        const int cur = t & 1;
        if (t+1<nk){
            a0 = aok0 ? *(const float4*)(Ap0 + (t+1)*16) : z4;
            a1 = aok1 ? *(const float4*)(Ap1 + (t+1)*16) : z4;
            b0 = bok0 ? *(const float4*)(Bp0 + (t+1)*16) : z4;
            b1 = bok1 ? *(const float4*)(Bp1 + (t+1)*16) : z4;
        }
        #pragma unroll
        for (int ks=0;ks<2;ks++){
            const int kb = ks*8;
            uint32_t af[2][4], bf[8][2];
            #pragma unroll
            for (int mt=0;mt<2;mt++){
                const int r = wm*32 + mt*16 + (lane>>2);
                af[mt][0] = As[cur][kb+(lane&3)  ][r];
                af[mt][1] = As[cur][kb+(lane&3)  ][r+8];
                af[mt][2] = As[cur][kb+(lane&3)+4][r];
                af[mt][3] = As[cur][kb+(lane&3)+4][r+8];
            }
            #pragma unroll
            for (int nt=0;nt<8;nt++){
                const int c = wN*64 + nt*8 + (lane>>2);
                bf[nt][0] = Bs[cur][kb+(lane&3)  ][c];
                bf[nt][1] = Bs[cur][kb+(lane&3)+4][c];
            }
            #pragma unroll
            for (int mt=0;mt<2;mt++)
                #pragma unroll
                for (int nt=0;nt<8;nt++) mma8(acc[mt][nt], af[mt], bf[nt]);
        }
        if (t+1<nk){ const int nxt = cur^1; stT(As[nxt],a0,a1); stT(Bs[nxt],b0,b1); }
        __syncthreads();
    }

    const float alpha = 0.125f;
    #pragma unroll
    for (int mt=0;mt<2;mt++){
        const int r0 = m0 + wm*32 + mt*16 + (lane>>2);
        #pragma unroll
        for (int nt=0;nt<8;nt++){
            const int gc = n0 + wN*64 + nt*8 + (lane&3)*2;
            if (r0 < Nn){
                if (gc+1 < Nn){
                    float2 v; v.x=acc[mt][nt][0]*alpha; v.y=acc[mt][nt][1]*alpha;
                    *(float2*)&Cs[(size_t)r0*SLD + gc] = v;
                } else if (gc < Nn) Cs[(size_t)r0*SLD + gc] = acc[mt][nt][0]*alpha;
            }
            if (r0+8 < Nn){
                if (gc+1 < Nn){
                    float2 v; v.x=acc[mt][nt][2]*alpha; v.y=acc[mt][nt][3]*alpha;
                    *(float2*)&Cs[(size_t)(r0+8)*SLD + gc] = v;
                } else if (gc < Nn) Cs[(size_t)(r0+8)*SLD + gc] = acc[mt][nt][2]*alpha;
            }
        }
    }
}

// =====================================================================
// mma_gemm_ctx: fused prune-mask + renorm + (pruned @ V).
// =====================================================================
__global__ __launch_bounds__(256,1)
void mma_gemm_ctx(const float* __restrict__ S, const float* __restrict__ QKV,
                  float* __restrict__ ctx, const int* __restrict__ counter,
                  const int* __restrict__ enabled)
{
    const int bh = blockIdx.z, b = bh / Hh, h = bh % Hh;
    const bool prune = ((*enabled) != 0) && ((*counter) > 50);
    const float* Sp = S + (size_t)bh*SB;
    const float* V  = QKV + (size_t)b*Nn*3*Cc + 2*(size_t)Cc + (size_t)h*Dh;
    const float* kp = g_keep + (size_t)b*KLD;   // 16B-aligned rows
    float* Cp = ctx + (size_t)b*Nn*Cc + (size_t)h*Dh;

    __shared__ uint32_t As[2][16][136];
    __shared__ uint32_t Bs[2][16][72];
    __shared__ float zsh[128];

    const int tid = threadIdx.x, lane = tid & 31, warp = tid >> 5;
    const int wm = warp & 3, wN = warp >> 2;
    const int m0 = blockIdx.y*128;

    const int ar = tid >> 2, ak = (tid & 3) << 2;
    const int gm0 = m0 + ar, gm1 = m0 + ar + 64;
    const bool aok0 = gm0 < Nn, aok1 = gm1 < Nn;
    const float keep0 = (prune && aok0) ? kp[gm0] : 1.f;
    const float keep1 = (prune && aok1) ? kp[gm1] : 1.f;
    const float* Ap0 = Sp + (size_t)(aok0 ? gm0 : 0)*SLD;
    const float* Ap1 = Sp + (size_t)(aok1 ? gm1 : 0)*SLD;
    const int bk = tid >> 4, bn = (tid & 15) << 2;
    const float* Bp = V + (size_t)bk*(3*Cc) + bn;

    const float4 z4 = make_float4(0.f,0.f,0.f,0.f);
    float z0 = 0.f, z1 = 0.f;

    auto ldrow = [&](const float* rowp, float keepi, int k0, bool ok, float& zacc)->float4{
        float4 v = z4;
        if (ok){
            const int c = k0 + ak;
            if (c + 3 < Nn) v = *(const float4*)(rowp + c);
            else {
                if (c   < Nn) v.x = rowp[c];
                if (c+1 < Nn) v.y = rowp[c+1];
                if (c+2 < Nn) v.z = rowp[c+2];
                if (c+3 < Nn) v.w = rowp[c+3];
            }
            if (keepi < 0.5f){
                float4 kv = z4;
                if (c + 3 < Nn) kv = *(const float4*)(kp + c);   // kp rows 16B-aligned now
                else {
                    if (c   < Nn) kv.x = kp[c];
                    if (c+1 < Nn) kv.y = kp[c+1];
                    if (c+2 < Nn) kv.z = kp[c+2];
                    if (c+3 < Nn) kv.w = kp[c+3];
                }
                v.x*=kv.x; v.y*=kv.y; v.z*=kv.z; v.w*=kv.w;
            }
            zacc += (v.x+v.y)+(v.z+v.w);
        }
        return v;
    };
    auto ldB = [&](int k0)->float4{
        return (k0 + bk < Nn) ? *(const float4*)(Bp + (size_t)k0*(3*Cc)) : z4;
    };
    auto stA = [&](int buf, const float4& v0, const float4& v1){
        As[buf][ak+0][ar]=f2tf(v0.x); As[buf][ak+1][ar]=f2tf(v0.y);
        As[buf][ak+2][ar]=f2tf(v0.z); As[buf][ak+3][ar]=f2tf(v0.w);
        As[buf][ak+0][ar+64]=f2tf(v1.x); As[buf][ak+1][ar+64]=f2tf(v1.y);
        As[buf][ak+2][ar+64]=f2tf(v1.z); As[buf][ak+3][ar+64]=f2tf(v1.w);
    };
    auto stB = [&](int buf, const float4& v){
        *(uint4*)&Bs[buf][bk][bn] = make_uint4(f2tf(v.x),f2tf(v.y),f2tf(v.z),f2tf(v.w));
    };

    float4 a0 = ldrow(Ap0, keep0, 0, aok0, z0);
    float4 a1 = ldrow(Ap1, keep1, 0, aok1, z1);
    float4 bv = ldB(0);
    stA(0,a0,a1); stB(0,bv); __syncthreads();

    float acc[2][4][4];
    #pragma unroll
    for (int i=0;i<2;i++)
        #pragma unroll
        for (int j=0;j<4;j++)
            #pragma unroll
            for (int q=0;q<4;q++) acc[i][j][q]=0.f;

    const int nk = (Nn + 15) >> 4;   // 65
    for (int t=0;t<nk;t++){
        const int cur = t & 1;
        if (t+1<nk){
            a0 = ldrow(Ap0, keep0, (t+1)*16, aok0, z0);
            a1 = ldrow(Ap1, keep1, (t+1)*16, aok1, z1);
            bv = ldB((t+1)*16);
        }
        #pragma unroll
        for (int ks=0;ks<2;ks++){
            const int kb = ks*8;
            uint32_t af[2][4], bf[4][2];
            #pragma unroll
            for (int mt=0;mt<2;mt++){
                const int r = wm*32 + mt*16 + (lane>>2);
                af[mt][0] = As[cur][kb+(lane&3)  ][r];
                af[mt][1] = As[cur][kb+(lane&3)  ][r+8];
                af[mt][2] = As[cur][kb+(lane&3)+4][r];
                af[mt][3] = As[cur][kb+(lane&3)+4][r+8];
            }
            #pragma unroll
            for (int nt=0;nt<4;nt++){
                const int c = wN*32 + nt*8 + (lane>>2);
                bf[nt][0] = Bs[cur][kb+(lane&3)  ][c];
                bf[nt][1] = Bs[cur][kb+(lane&3)+4][c];
            }
            #pragma unroll
            for (int mt=0;mt<2;mt++)
                #pragma unroll
                for (int nt=0;nt<4;nt++) mma8(acc[mt][nt], af[mt], bf[nt]);
        }
        if (t+1<nk){ const int nxt = cur^1; stA(nxt,a0,a1); stB(nxt,bv); }
        __syncthreads();
    }

    z0 += __shfl_xor_sync(0xffffffffu, z0, 1);
    z0 += __shfl_xor_sync(0xffffffffu, z0, 2);
    z1 += __shfl_xor_sync(0xffffffffu, z1, 1);
    z1 += __shfl_xor_sync(0xffffffffu, z1, 2);
    if ((lane & 3) == 0){ zsh[ar] = z0; zsh[ar+64] = z1; }
    __syncthreads();

    #pragma unroll
    for (int mt=0;mt<2;mt++){
        const int lr = wm*32 + mt*16 + (lane>>2);
        const int r0 = m0 + lr;
        const float iz0 = prune ? 1.f/(zsh[lr]   + 1e-8f) : 1.f;
        const float iz1 = prune ? 1.f/(zsh[lr+8] + 1e-8f) : 1.f;
        #pragma unroll
        for (int nt=0;nt<4;nt++){
            const int gc = wN*32 + nt*8 + (lane&3)*2;
            if (r0 < Nn){
                float2 v; v.x=acc[mt][nt][0]*iz0; v.y=acc[mt][nt][1]*iz0;
                *(float2*)&Cp[(size_t)r0*Cc + gc] = v;
            }
            if (r0+8 < Nn){
                float2 v; v.x=acc[mt][nt][2]*iz1; v.y=acc[mt][nt][3]*iz1;
                *(float2*)&Cp[(size_t)(r0+8)*Cc + gc] = v;
            }
        }
    }
}

// ---------------- row softmax (vectorized) ----------------
__global__ __launch_bounds__(256)
void softmax_kernel(float* __restrict__ S)
{
    const int r = blockIdx.x;
    float* row = S + (size_t)(r / Nn)*SB + (size_t)(r % Nn)*SLD;
    const int t = threadIdx.x;
    __shared__ float red[256];

    float4 v = ((const float4*)row)[t];
    const float last = row[1024];
    float mx = fmaxf(fmaxf(v.x,v.y), fmaxf(v.z,v.w));
    mx = fmaxf(mx, last);
    red[t] = mx; __syncthreads();
    for (int s=128;s>0;s>>=1){ if (t<s) red[t]=fmaxf(red[t],red[t+s]); __syncthreads(); }
    mx = red[0]; __syncthreads();

    float4 e;
    e.x = __expf(v.x-mx); e.y = __expf(v.y-mx);
    e.z = __expf(v.z-mx); e.w = __expf(v.w-mx);
    const float el = __expf(last-mx);
    float sm = (e.x+e.y)+(e.z+e.w);
    if (t==0) sm += el;
    red[t] = sm; __syncthreads();
    for (int s=128;s>0;s>>=1){ if (t<s) red[t]+=red[t+s]; __syncthreads(); }
    const float inv = 1.f/red[0];
    e.x*=inv; e.y*=inv; e.z*=inv; e.w*=inv;
    ((float4*)row)[t] = e;
    if (t==0) row[1024] = el*inv;
}

// ---------------- zero small scratch ----------------
__global__ void zero_scratch_kernel()
{
    int idx = blockIdx.x*256 + threadIdx.x;
    if (idx < BH*Nn) g_patch[idx] = 0.f;
    if (idx < Bsz*KLD) g_keep[idx] = 0.f;
    if (idx < Nn) g_cnt[idx] = 0.f;
}

// ---------------- column sums per (b,h) ----------------
__global__ __launch_bounds__(256)
void colsum_kernel(const float* __restrict__ S)
{
    const int bh = blockIdx.x;
    const int i0 = blockIdx.y*129, i1 = min(i0+129, Nn);
    const float* Sb = S + (size_t)bh*SB;
    const int t = threadIdx.x;

    float4 acc = make_float4(0.f,0.f,0.f,0.f);
    float accl = 0.f;
    for (int i=i0;i<i1;i++){
        const float* row = Sb + (size_t)i*SLD;
        const float4 v = ((const float4*)row)[t];
        acc.x+=v.x; acc.y+=v.y; acc.z+=v.z; acc.w+=v.w;
        if (t==0) accl += row[1024];
    }
    float* base = &g_patch[bh*Nn];
    atomicAdd(&base[t*4+0], acc.x);
    atomicAdd(&base[t*4+1], acc.y);
    atomicAdd(&base[t*4+2], acc.z);
    atomicAdd(&base[t*4+3], acc.w);
    if (t==0) atomicAdd(&base[1024], accl);
}

// ---------------- combine patch means + exploration ----------------
__global__ __launch_bounds__(256)
void ucb_combine_kernel(const float* __restrict__ ucb_score, const int* __restrict__ counter)
{
    const int b = blockIdx.x, t = threadIdx.x;
    const float logc = logf((float)(*counter) + 1.0f);
    for (int jj=t; jj<Nn-1; jj+=256){
        const int j = jj + 1;
        float s = 0.f;
        #pragma unroll
        for (int h=0; h<Hh; h++){
            const float expl = sqrtf(logc / (ucb_score[h*Nn + j] + 1e-6f));
            s += g_patch[(b*Hh + h)*Nn + j] * (1.f/(float)Nn) + expl;
        }
        g_gucb[b*(Nn-1) + jj] = s * (1.f/(float)Hh);
    }
}

// ---------------- exact top-k (bitonic; ties -> lower index) ----------------
__global__ __launch_bounds__(512)
void topk_kernel()
{
    __shared__ float sv[1024];
    __shared__ int   si[1024];
    const int b = blockIdx.x, t = threadIdx.x;

    for (int j=t;j<1024;j+=512){ sv[j] = g_gucb[b*1024 + j]; si[j] = j; }
    __syncthreads();

    for (int k=2;k<=1024;k<<=1){
        for (int j=k>>1;j>0;j>>=1){
            for (int i=t;i<1024;i+=512){
                const int ixj = i ^ j;
                if (ixj > i){
                    float v1 = sv[i], v2 = sv[ixj];
                    int  i1 = si[i],  i2 = si[ixj];
                    const bool before = (v1 > v2) || (v1 == v2 && i1 < i2);
                    const bool dirDesc = ((i & k) == 0);
                    if (dirDesc ? (!before) : before){
                        sv[i]=v2; sv[ixj]=v1; si[i]=i2; si[ixj]=i1;
                    }
                }
            }
            __syncthreads();
        }
    }

    if (t < KSEL){
        const int tok = si[t] + 1;
        g_keep[b*KLD + tok] = 1.f;
        atomicAdd(&g_cnt[tok], 1.f);
    }
    if (t == 0) g_keep[b*KLD + 0] = 1.f;
}

// ---------------- score_delta ----------------
__global__ void score_delta_kernel(float* __restrict__ out2)
{
    int idx = blockIdx.x*256 + threadIdx.x;
    if (idx < Hh*Nn) out2[idx] = g_cnt[idx % Nn] * (1.f/(float)Bsz);
}

// =======================================================================
extern "C" void kernel_launch(void* const* d_in, const int* in_sizes, int n_in,
                              void* d_out, int out_size)
{
    const float* x       = (const float*)d_in[0];
    const float* ucbsc   = (const float*)d_in[1];
    const float* Wqkv    = (const float*)d_in[2];
    const float* Wproj   = (const float*)d_in[3];
    const float* bproj   = (const float*)d_in[4];
    const int*   counter = (const int*)d_in[5];
    const int*   enabled = (const int*)d_in[6];
    float* out = (float*)d_out;

    float *qkv, *S, *ctx;
    cudaGetSymbolAddress((void**)&qkv, g_qkv);
    cudaGetSymbolAddress((void**)&S,   g_S);
    cudaGetSymbolAddress((void**)&ctx, g_ctx);

    // 0) zero scratch (independent)
    zero_scratch_kernel<<<(BH*Nn + 255)/256, 256>>>();

    // 1) qkv = x @ W_qkv   [4100 x 2304 x 768]
    {
        dim3 grid(2304/128, (Bsz*Nn + 127)/128);
        mma_gemm_nn<false><<<grid, 256>>>(x, Wqkv, nullptr, qkv,
                                          Bsz*Nn, 3*Cc, Cc, Cc, 3*Cc, 3*Cc);
    }
    // 2) S = 0.125 * Q @ K^T  per (b,h)
    {
        dim3 grid((Nn+127)/128, (Nn+127)/128, BH);
        mma_gemm_qk<<<grid, 256>>>(qkv, S);
    }
    // 3) softmax rows
    softmax_kernel<<<BH*Nn, 256>>>(S);

    // 4) column sums, ucb combine, top-k
    { dim3 grid(BH, 8); colsum_kernel<<<grid, 256>>>(S); }
    ucb_combine_kernel<<<Bsz, 256>>>(ucbsc, counter);
    topk_kernel<<<Bsz, 512>>>();

    // 5) fused prune+renorm+context GEMM
    {
        dim3 grid(1, (Nn+127)/128, BH);
        mma_gemm_ctx<<<grid, 256>>>(S, qkv, ctx, counter, enabled);
    }
    // 6) out = ctx @ W_proj + b_proj
    {
        dim3 grid(768/128, (Bsz*Nn + 127)/128);
        mma_gemm_nn<true><<<grid, 256>>>(ctx, Wproj, bproj, out,
                                         Bsz*Nn, Cc, Cc, Cc, Cc, Cc);
    }
    // 7) score_delta
    if (out_size >= Bsz*Nn*Cc + Hh*Nn) {
        score_delta_kernel<<<(Hh*Nn + 255)/256, 256>>>(out + (size_t)Bsz*Nn*Cc);
    }
}